// round 2
// baseline (speedup 1.0000x reference)
#include <cuda_runtime.h>
#include <cstdint>

#define N_   32
#define C_   256
#define O_   256
#define HW_  56
#define PIX  3136          // 56*56
#define CNTS 802816.0f     // 256*56*56 per-sample element count
#define EPSF 1e-5f

// ---------------- device scratch (no allocations allowed) ----------------
__device__ float    g_asum[N_];
__device__ float    g_alpha[N_];
__device__ float    g_m[O_];
__device__ __align__(16) unsigned g_wbits[O_ * 72];      // [o][tap][word] 9 taps * 8 words
__device__ int      g_pw[O_ * 9];                        // popc of wbits per (o,tap)
__device__ __align__(16) unsigned g_xbits[(size_t)N_ * PIX * 8]; // [n][pix][word]
__device__ int      g_xz_count;
__device__ int      g_wz_count;
__device__ int      g_xz_list[4096];                     // linear idx into x
__device__ int      g_wz_list[64];                       // linear idx into w

// ---------------- K0: zero counters/accumulators ----------------
__global__ void k_zero() {
    int t = blockIdx.x * blockDim.x + threadIdx.x;
    if (t < N_) g_asum[t] = 0.f;
    if (t < O_ * 9) g_pw[t] = 0;
    if (t == 0) { g_xz_count = 0; g_wz_count = 0; }
}

// ---------------- K1: pack x sign bits + accumulate sum|x| ----------------
// grid = 32 n * 8 words * 4 pixel-chunks = 1024 blocks, 256 threads
__global__ void k_packx(const float* __restrict__ x) {
    int b     = blockIdx.x;
    int n     = b >> 5;
    int word  = (b >> 2) & 7;
    int chunk = b & 3;
    int tid   = threadIdx.x;
    int pixBase = chunk * 1024;

    unsigned bits[4] = {0u, 0u, 0u, 0u};
    float s = 0.f;

    for (int c = 0; c < 32; c++) {
        int ch = word * 32 + c;
        const float* row = x + ((size_t)(n * C_ + ch)) * PIX + pixBase;
#pragma unroll
        for (int j = 0; j < 4; j++) {
            int p = tid + j * 256;
            if (pixBase + p < PIX) {
                float v = row[p];
                s += fabsf(v);
                bits[j] |= ((unsigned)(v < 0.f)) << c;
                if (v == 0.f) {                  // exact-zero: record for correction
                    int idx = atomicAdd(&g_xz_count, 1);
                    if (idx < 4096) g_xz_list[idx] = (n * C_ + ch) * PIX + pixBase + p;
                }
            }
        }
    }
#pragma unroll
    for (int j = 0; j < 4; j++) {
        int p = tid + j * 256;
        if (pixBase + p < PIX)
            g_xbits[((size_t)n * PIX + pixBase + p) * 8 + word] = bits[j];
    }

    __shared__ float red[256];
    red[tid] = s;
    __syncthreads();
    for (int st = 128; st > 0; st >>= 1) {
        if (tid < st) red[tid] += red[tid + st];
        __syncthreads();
    }
    if (tid == 0) atomicAdd(&g_asum[n], red[0]);
}

// ---------------- K2: pack w sign bits, per-tap popcounts, m[o] ----------------
// grid = 256 blocks (one per o), 256 threads (8 warps = 8 channel-words)
__global__ void k_packw(const float* __restrict__ w) {
    int o = blockIdx.x;
    int tid = threadIdx.x;
    int j = tid >> 5, lane = tid & 31;
    int c = j * 32 + lane;

    float s = 0.f;
#pragma unroll
    for (int tap = 0; tap < 9; tap++) {
        float v = w[((size_t)(o * C_ + c)) * 9 + tap];
        s += fabsf(v);
        unsigned bal = __ballot_sync(0xffffffffu, v < 0.f);
        if (lane == 0) {
            g_wbits[o * 72 + tap * 8 + j] = bal;
            atomicAdd(&g_pw[o * 9 + tap], __popc(bal));
        }
        if (v == 0.f) {
            int idx = atomicAdd(&g_wz_count, 1);
            if (idx < 64) g_wz_list[idx] = (o * C_ + c) * 9 + tap;
        }
    }
    __shared__ float red[256];
    red[tid] = s;
    __syncthreads();
    for (int st = 128; st > 0; st >>= 1) {
        if (tid < st) red[tid] += red[tid + st];
        __syncthreads();
    }
    if (tid == 0) g_m[o] = red[0] / 2304.f;
}

// ---------------- K3: finalize alpha ----------------
__global__ void k_alpha() {
    int n = threadIdx.x;
    if (n < N_) g_alpha[n] = fmaxf(2.f * g_asum[n] / CNTS, EPSF);
}

// ---------------- K4: XNOR-popcount conv ----------------
// block = (n, 4 output rows); 224 threads = 4 rows x 56 cols; loops all 256 o.
// SMEM words: ws 18432 | pw 2304 | ms 256 | xt 6*58*9 = 3132  -> 96496 B
#define SM_WS  0
#define SM_PW  18432
#define SM_MS  (18432 + 2304)
#define SM_XT  (18432 + 2304 + 256)
#define CONV_SMEM ((18432 + 2304 + 256 + 6*58*9) * 4)

__global__ __launch_bounds__(224, 2) void k_conv(float* __restrict__ out) {
    extern __shared__ unsigned sm[];
    unsigned* ws = sm + SM_WS;
    int*      pw = (int*)(sm + SM_PW);
    float*    ms = (float*)(sm + SM_MS);
    unsigned* xt = sm + SM_XT;

    int b = blockIdx.x;
    int n = b / 14;
    int ohBase = (b % 14) * 4;
    int tid = threadIdx.x;

    for (int i = tid; i < 4608; i += 224)
        ((uint4*)ws)[i] = ((const uint4*)g_wbits)[i];
    for (int i = tid; i < 2304; i += 224) pw[i] = g_pw[i];
    for (int i = tid; i < 256; i += 224) ms[i] = g_m[i];

    // x tile: 6 rows x 58 cols, padded pixel stride 9 words (bank-conflict-free)
    for (int u = tid; u < 6 * 58 * 2; u += 224) {
        int half = u & 1;
        int t = u >> 1;
        int col = t % 58;
        int rr = t / 58;
        int ih = ohBase - 1 + rr;
        int iw = col - 1;
        uint4 v = make_uint4(0u, 0u, 0u, 0u);
        if (ih >= 0 && ih < HW_ && iw >= 0 && iw < HW_)
            v = *(const uint4*)&g_xbits[((size_t)n * PIX + ih * HW_ + iw) * 8 + half * 4];
        unsigned* d = &xt[(rr * 58 + col) * 9 + half * 4];
        d[0] = v.x; d[1] = v.y; d[2] = v.z; d[3] = v.w;
    }
    __syncthreads();

    int r = tid / 56, ow = tid % 56;
    int oh = ohBase + r;

    // 3x3x8-word x window in registers, reused across all 256 o
    unsigned X[72];
#pragma unroll
    for (int kh = 0; kh < 3; kh++)
#pragma unroll
        for (int kw = 0; kw < 3; kw++) {
            const unsigned* p = &xt[((r + kh) * 58 + ow + kw) * 9];
#pragma unroll
            for (int k = 0; k < 8; k++) X[(kh * 3 + kw) * 8 + k] = p[k];
        }

    // invalid-tap mask for padding (halo bits are 0 => tap contributed 256-2*PW; remove it)
    unsigned bm = 0;
#pragma unroll
    for (int t = 0; t < 9; t++) {
        int kh = t / 3, kw = t % 3;
        bool inv = (kh == 0 && oh == 0) || (kh == 2 && oh == HW_ - 1) ||
                   (kw == 0 && ow == 0) || (kw == 2 && ow == HW_ - 1);
        if (inv) bm |= 1u << t;
    }

    float al = g_alpha[n];
    float* obase = out + (size_t)n * O_ * PIX + ohBase * HW_ + tid;

    for (int o = 0; o < O_; o++) {
        const uint4* wp = (const uint4*)&ws[o * 72];
        int acc = 0;
#pragma unroll
        for (int t = 0; t < 9; t++) {
            uint4 wa = wp[t * 2];
            uint4 wb = wp[t * 2 + 1];
            const unsigned* Xp = &X[t * 8];
            acc += __popc(Xp[0] ^ wa.x) + __popc(Xp[1] ^ wa.y) +
                   __popc(Xp[2] ^ wa.z) + __popc(Xp[3] ^ wa.w) +
                   __popc(Xp[4] ^ wb.x) + __popc(Xp[5] ^ wb.y) +
                   __popc(Xp[6] ^ wb.z) + __popc(Xp[7] ^ wb.w);
        }
        int S = 2304 - 2 * acc;
        if (bm) {
            unsigned m2 = bm;
            while (m2) {
                int t = __ffs(m2) - 1;
                m2 &= m2 - 1;
                S -= 256 - 2 * pw[o * 9 + t];
            }
        }
        obase[(size_t)o * PIX] = al * ms[o] * (float)S;
    }
}

// ---------------- K5: exact correction for x==0 elements ----------------
__global__ void k_xzero(float* __restrict__ out) {
    int zc = g_xz_count;
    if (zc > 4096) zc = 4096;
    long total = (long)zc * 2304;
    for (long i = (long)blockIdx.x * blockDim.x + threadIdx.x; i < total;
         i += (long)gridDim.x * blockDim.x) {
        int z = (int)(i / 2304);
        int q = (int)(i % 2304);
        int o = q / 9, tap = q % 9;
        int li = g_xz_list[z];
        int pix = li % PIX;
        int ch = (li / PIX) & 255;
        int n = li / (PIX * C_);
        int h = pix / HW_, wv = pix % HW_;
        int kh = tap / 3, kw = tap % 3;
        int oh = h + 1 - kh, ow = wv + 1 - kw;
        if ((unsigned)oh < HW_ && (unsigned)ow < HW_) {
            unsigned bit = (g_wbits[o * 72 + tap * 8 + (ch >> 5)] >> (ch & 31)) & 1u;
            float bw = bit ? -1.f : 1.f;   // encoded product was (+1)*bw; truth is 0
            atomicAdd(&out[((size_t)(n * O_ + o)) * PIX + oh * HW_ + ow],
                      -bw * g_alpha[n] * g_m[o]);
        }
    }
}

// ---------------- K6: exact correction for w==0 elements ----------------
__global__ void k_wzero(const float* __restrict__ x, float* __restrict__ out) {
    int zc = g_wz_count;
    if (zc > 64) zc = 64;
    long total = (long)zc * N_ * PIX;
    for (long i = (long)blockIdx.x * blockDim.x + threadIdx.x; i < total;
         i += (long)gridDim.x * blockDim.x) {
        int z = (int)(i / ((long)N_ * PIX));
        int rte = (int)(i % ((long)N_ * PIX));
        int n = rte / PIX, pix = rte % PIX;
        int oh = pix / HW_, ow = pix % HW_;
        int li = g_wz_list[z];
        int tap = li % 9;
        int ch = (li / 9) & 255;
        int o = li / (9 * C_);
        int kh = tap / 3, kw = tap % 3;
        int ih = oh - 1 + kh, iw = ow - 1 + kw;
        if ((unsigned)ih < HW_ && (unsigned)iw < HW_) {
            float xv = x[((size_t)(n * C_ + ch)) * PIX + ih * HW_ + iw];
            if (xv != 0.f) {               // x==0 already fixed by k_xzero
                float bx = (xv < 0.f) ? -1.f : 1.f;  // encoded product was bx*(+1)
                atomicAdd(&out[((size_t)(n * O_ + o)) * PIX + pix],
                          -bx * g_alpha[n] * g_m[o]);
            }
        }
    }
}

// ---------------- launch ----------------
extern "C" void kernel_launch(void* const* d_in, const int* in_sizes, int n_in,
                              void* d_out, int out_size) {
    const float* x = (const float*)d_in[0];
    const float* w = (const float*)d_in[1];
    float* out = (float*)d_out;

    cudaFuncSetAttribute(k_conv, cudaFuncAttributeMaxDynamicSharedMemorySize, CONV_SMEM);

    k_zero<<<9, 256>>>();
    k_packx<<<1024, 256>>>(x);
    k_packw<<<256, 256>>>(w);
    k_alpha<<<1, 32>>>();
    k_conv<<<448, 224, CONV_SMEM>>>(out);
    k_xzero<<<64, 256>>>(out);
    k_wzero<<<128, 256>>>(x, out);
}